// round 10
// baseline (speedup 1.0000x reference)
#include <cuda_runtime.h>
#include <math.h>

#define BATCH 256
#define TSTEPS 50
#define INSZ 400
#define G4 1024
#define GAMMA 0.95f
#define EPSF 1e-8f

// ---------- device scratch ----------
__device__ float g_xw[TSTEPS * BATCH * G4];
__device__ float g_h[BATCH * 256];
__device__ float g_c[BATCH * 256];
__device__ float g_r[BATCH * 256];
__device__ float g_M[BATCH * 256 * 64];
__device__ float g_wr[BATCH * 4 * 256];
__device__ float g_wu[BATCH * 256];

__device__ __forceinline__ float sigf(float x) { return 1.0f / (1.0f + expf(-x)); }

// packed f32x2 helpers (bit-identical to scalar fp32 FMA per lane)
__device__ __forceinline__ void ffma2(unsigned long long& d, unsigned long long a, unsigned long long b) {
    asm("fma.rn.f32x2 %0, %1, %2, %0;" : "+l"(d) : "l"(a), "l"(b));
}
__device__ __forceinline__ unsigned long long pk2(float x, float y) {
    unsigned long long r;
    asm("mov.b64 %0, {%1, %2};" : "=l"(r) : "f"(x), "f"(y));
    return r;
}
__device__ __forceinline__ void upk2(float& x, float& y, unsigned long long v) {
    asm("mov.b64 {%0, %1}, %2;" : "=f"(x), "=f"(y) : "l"(v));
}

// ---------- init ----------
__global__ void k_init() {
    int i = blockIdx.x * blockDim.x + threadIdx.x;
    if (i < BATCH * 256 * 64) g_M[i] = 1e-6f;
    if (i < BATCH * 1024) g_wr[i] = 1.0f / 256.0f;
    if (i < BATCH * 256) {
        g_h[i] = 0.0f; g_c[i] = 0.0f; g_r[i] = 0.0f;
        g_wu[i] = 1.0f / 256.0f;
    }
}

// ---------- K1: time-parallel input GEMM (f32x2 packed) ----------
__global__ __launch_bounds__(256) void k1_xw(
    const float* __restrict__ X, const int* __restrict__ tgt,
    const float* __restrict__ Wih, const float* __restrict__ bl)
{
    __shared__ float As[16][68];
    __shared__ float Bs[16][64];
    const int tid = threadIdx.x;
    const int tx = tid & 15, ty = tid >> 4;
    const int m0 = blockIdx.y * 64, n0 = blockIdx.x * 64;
    const int arow = tid >> 2, akq = tid & 3;
    const int bk = tid >> 4, bc = tid & 15;
    unsigned long long accp[4][2] = {};
    for (int kt = 0; kt < 25; kt++) {
        float4 av = *(const float4*)(X + (size_t)(m0 + arow) * INSZ + kt * 16 + akq * 4);
        As[akq * 4 + 0][arow] = av.x; As[akq * 4 + 1][arow] = av.y;
        As[akq * 4 + 2][arow] = av.z; As[akq * 4 + 3][arow] = av.w;
        *(float4*)&Bs[bk][bc * 4] =
            *(const float4*)(Wih + (size_t)(kt * 16 + bk) * G4 + n0 + bc * 4);
        __syncthreads();
#pragma unroll
        for (int k = 0; k < 16; k++) {
            float4 a = *(float4*)&As[k][ty * 4];
            unsigned long long b0 = *(unsigned long long*)&Bs[k][tx * 4];
            unsigned long long b1 = *(unsigned long long*)&Bs[k][tx * 4 + 2];
            unsigned long long ax = pk2(a.x, a.x);
            unsigned long long ay = pk2(a.y, a.y);
            unsigned long long az = pk2(a.z, a.z);
            unsigned long long aw = pk2(a.w, a.w);
            ffma2(accp[0][0], ax, b0); ffma2(accp[0][1], ax, b1);
            ffma2(accp[1][0], ay, b0); ffma2(accp[1][1], ay, b1);
            ffma2(accp[2][0], az, b0); ffma2(accp[2][1], az, b1);
            ffma2(accp[3][0], aw, b0); ffma2(accp[3][1], aw, b1);
        }
        __syncthreads();
    }
#pragma unroll
    for (int i = 0; i < 4; i++) {
        float a0, a1, a2, a3;
        upk2(a0, a1, accp[i][0]);
        upk2(a2, a3, accp[i][1]);
        float accv[4] = { a0, a1, a2, a3 };
        int m = m0 + ty * 4 + i;
        int bb = m / TSTEPS, t = m % TSTEPS;
        const float* offrow = (t > 0) ? (Wih + (size_t)(400 + tgt[m - 1]) * G4) : (const float*)0;
        float* dst = g_xw + ((size_t)t * BATCH + bb) * G4 + n0 + tx * 4;
#pragma unroll
        for (int j = 0; j < 4; j++) {
            int c = n0 + tx * 4 + j;
            float v = accv[j] + bl[c];
            if (offrow) v += offrow[c];
            dst[j] = v;
        }
    }
}

// ---------- K2: recurrent GEMM + LSTM, double-buffered + f32x2 ----------
__global__ __launch_bounds__(256) void k2_step(
    const float* __restrict__ Wih, const float* __restrict__ Whh, int t)
{
    __shared__ float As[2][16][34];     // 136B rows: float2 loads 8B-aligned
    __shared__ float Bs[2][16][68];     // [k][u*4+g], padded
    const int tid = threadIdx.x;
    const int tx = tid & 15, ty = tid >> 4;
    const int b0 = blockIdx.x * 32, u0 = blockIdx.y * 16;
    const int arow = tid >> 3, akq = tid & 7;
    const int bk = tid >> 4, bu = tid & 15;
    const float* WihR = Wih + (size_t)405 * G4;

    // prefetch epilogue operands
    const int uP = u0 + tx;
    const int bP0 = b0 + ty * 2, bP1 = bP0 + 1;
    const float* xwA = g_xw + ((size_t)t * BATCH + bP0) * G4;
    const float* xwB = g_xw + ((size_t)t * BATCH + bP1) * G4;
    float xA0 = xwA[uP], xA1 = xwA[256 + uP], xA2 = xwA[512 + uP], xA3 = xwA[768 + uP];
    float xB0 = xwB[uP], xB1 = xwB[256 + uP], xB2 = xwB[512 + uP], xB3 = xwB[768 + uP];
    float cA = g_c[bP0 * 256 + uP], cB = g_c[bP1 * 256 + uP];

    // tile 0 -> buffer 0
    {
        float2 av = *(const float2*)(g_r + (size_t)(b0 + arow) * 256 + akq * 2);
        As[0][akq * 2][arow] = av.x; As[0][akq * 2 + 1][arow] = av.y;
        const float* wrow = WihR + (size_t)bk * G4 + u0 + bu;
        Bs[0][bk][bu * 4 + 0] = wrow[0];
        Bs[0][bk][bu * 4 + 1] = wrow[256];
        Bs[0][bk][bu * 4 + 2] = wrow[512];
        Bs[0][bk][bu * 4 + 3] = wrow[768];
    }
    __syncthreads();

    unsigned long long accp[2][2] = {};
    for (int kt = 0; kt < 32; kt++) {
        const int cur = kt & 1;
        float2 avn = make_float2(0.f, 0.f);
        float bgn0 = 0.f, bgn1 = 0.f, bgn2 = 0.f, bgn3 = 0.f;
        if (kt < 31) {
            const int kn = kt + 1;
            const float* src = (kn < 16) ? g_r : g_h;
            avn = *(const float2*)(src + (size_t)(b0 + arow) * 256 + (kn & 15) * 16 + akq * 2);
            const float* W = (kn < 16) ? WihR : Whh;
            const float* wrow = W + (size_t)((kn & 15) * 16 + bk) * G4 + u0 + bu;
            bgn0 = wrow[0]; bgn1 = wrow[256]; bgn2 = wrow[512]; bgn3 = wrow[768];
        }
#pragma unroll
        for (int k = 0; k < 16; k++) {
            float2 a = *(float2*)&As[cur][k][ty * 2];
            unsigned long long b0p = *(unsigned long long*)&Bs[cur][k][tx * 4];
            unsigned long long b1p = *(unsigned long long*)&Bs[cur][k][tx * 4 + 2];
            unsigned long long a0p = pk2(a.x, a.x);
            unsigned long long a1p = pk2(a.y, a.y);
            ffma2(accp[0][0], a0p, b0p); ffma2(accp[0][1], a0p, b1p);
            ffma2(accp[1][0], a1p, b0p); ffma2(accp[1][1], a1p, b1p);
        }
        if (kt < 31) {
            const int nxt = 1 - cur;
            As[nxt][akq * 2][arow] = avn.x; As[nxt][akq * 2 + 1][arow] = avn.y;
            Bs[nxt][bk][bu * 4 + 0] = bgn0;
            Bs[nxt][bk][bu * 4 + 1] = bgn1;
            Bs[nxt][bk][bu * 4 + 2] = bgn2;
            Bs[nxt][bk][bu * 4 + 3] = bgn3;
            __syncthreads();
        }
    }
    {
        float g0, g1, g2, g3;
        upk2(g0, g1, accp[0][0]); upk2(g2, g3, accp[0][1]);
        float gi = g0 + xA0, gf = g1 + xA1, gg = g2 + xA2, go = g3 + xA3;
        float cc = sigf(gf) * cA + sigf(gi) * tanhf(gg);
        g_c[bP0 * 256 + uP] = cc;
        g_h[bP0 * 256 + uP] = sigf(go) * tanhf(cc);
    }
    {
        float g0, g1, g2, g3;
        upk2(g0, g1, accp[1][0]); upk2(g2, g3, accp[1][1]);
        float gi = g0 + xB0, gf = g1 + xB1, gg = g2 + xB2, go = g3 + xB3;
        float cc = sigf(gf) * cB + sigf(gi) * tanhf(gg);
        g_c[bP1 * 256 + uP] = cc;
        g_h[bP1 * 256 + uP] = sigf(go) * tanhf(cc);
    }
}

// ---------- K4: 512-thread short-critical-path memory module ----------
#define O_M     0        // 256*65
#define O_K     16640    // 256
#define O_SIM   16896    // 1024
#define O_WW    17920    // 1024
#define O_WU    18944    // 256
#define O_H     19200    // 256
#define O_RD    19456    // 256
#define O_PR    19712    // 512
#define O_WP    20224    // 40
#define O_EX    20264    // 16
#define O_SOFT  20280    // 16
#define O_LU    20296    // 4 (int)
#define O_PART  20300    // 16*264
#define K4_FLOATS 24524
#define K4_BYTES (K4_FLOATS * 4)

__global__ __launch_bounds__(512) void k4_mem(
    const float* __restrict__ Wkp, const float* __restrict__ bkp,
    const float* __restrict__ Wout, const float* __restrict__ bout,
    float* __restrict__ out, int t)
{
    extern __shared__ float sm[];
    float* sM     = sm + O_M;
    float* sk     = sm + O_K;
    float* ssim   = sm + O_SIM;
    float* sww    = sm + O_WW;
    float* swu    = sm + O_WU;
    float* sh     = sm + O_H;
    float* sreads = sm + O_RD;
    float* spR    = sm + O_PR;
    float* swp    = sm + O_WP;
    float* sex    = sm + O_EX;
    float* ssoft  = sm + O_SOFT;
    int*   slu    = (int*)(sm + O_LU);
    float* spart  = sm + O_PART;

    const int b = blockIdx.x;
    const int tid = threadIdx.x;
    const int lane = tid & 31, wid = tid >> 5;

    if (tid < 256) {
        swu[tid] = g_wu[b * 256 + tid];
        sh[tid]  = g_h[b * 256 + tid];
    }
    {
        const float4* gm4 = (const float4*)(g_M + (size_t)b * 16384);
#pragma unroll
        for (int e = 0; e < 8; e++) {
            float4 v = gm4[e * 512 + tid];
            int gidx = (e * 512 + tid) * 4;
            int n = gidx >> 6, d = gidx & 63;
            float* dst = sM + n * 65 + d;
            dst[0] = v.x; dst[1] = v.y; dst[2] = v.z; dst[3] = v.w;
        }
    }
    __syncthreads();

    // kp GEMV: 16-way k-split
    {
        const int kbase = wid * 16;
        float hreg[16];
#pragma unroll
        for (int kk = 0; kk < 16; kk++) hreg[kk] = sh[kbase + kk];
#pragma unroll
        for (int g = 0; g < 9; g++) {
            int col = g * 32 + lane;
            if (col < 260) {
                const float* wp = Wkp + (size_t)kbase * 260 + col;
                float part = 0.0f;
#pragma unroll
                for (int kk = 0; kk < 16; kk++)
                    part += hreg[kk] * wp[(size_t)kk * 260];
                spart[wid * 264 + col] = part;
            }
        }
    }
    __syncthreads();
    if (tid < 260) {
        float s = bkp[tid];
#pragma unroll
        for (int w = 0; w < 16; w++) s += spart[w * 264 + tid];
        if (tid < 256) sk[tid] = tanhf(s);
        else sex[4 + (tid - 256)] = sigf(s);
    }
    __syncthreads();

    // key norms (warps 0-3) || top-4 least-used (warp 4)
    if (wid < 4) {
        float v0 = sk[wid * 64 + lane], v1 = sk[wid * 64 + lane + 32];
        float s = v0 * v0 + v1 * v1;
#pragma unroll
        for (int o = 16; o > 0; o >>= 1) s += __shfl_xor_sync(0xffffffffu, s, o);
        if (lane == 0) sex[wid] = 1.0f / (sqrtf(s) + EPSF);
    } else if (wid == 4) {
        float v[8];
#pragma unroll
        for (int j = 0; j < 8; j++) v[j] = swu[j * 32 + lane];
#pragma unroll
        for (int r = 0; r < 4; r++) {
            float bv = v[0]; int bi = lane;
#pragma unroll
            for (int j = 1; j < 8; j++) {
                int idx = j * 32 + lane;
                if (v[j] < bv) { bv = v[j]; bi = idx; }
            }
#pragma unroll
            for (int o = 16; o > 0; o >>= 1) {
                float ov = __shfl_xor_sync(0xffffffffu, bv, o);
                int   oi = __shfl_xor_sync(0xffffffffu, bi, o);
                if (ov < bv || (ov == bv && oi < bi)) { bv = ov; bi = oi; }
            }
            if (lane == 0) slu[r] = bi;
#pragma unroll
            for (int j = 0; j < 8; j++)
                if (bi == j * 32 + lane) v[j] = 3.0e38f;
        }
    }
    __syncthreads();

    if (tid < 256) {
        float a0 = sex[4], a1 = sex[5], a2 = sex[6], a3 = sex[7];
        const float* wr = g_wr + (size_t)b * 1024;
        float4 w;
        w.x = a0 * wr[tid]       + (1.0f - a0) * ((tid == slu[0]) ? 1.0f : 0.0f);
        w.y = a1 * wr[256 + tid] + (1.0f - a1) * ((tid == slu[1]) ? 1.0f : 0.0f);
        w.z = a2 * wr[512 + tid] + (1.0f - a2) * ((tid == slu[2]) ? 1.0f : 0.0f);
        w.w = a3 * wr[768 + tid] + (1.0f - a3) * ((tid == slu[3]) ? 1.0f : 0.0f);
        *(float4*)&sww[tid * 4] = w;
    }
    __syncthreads();

    // erase + additive write; persist M
    {
        const int d = tid & 63, nb = tid >> 6;
        const int lu0 = slu[0];
        const float k0 = sk[d], k1 = sk[64 + d], k2 = sk[128 + d], k3 = sk[192 + d];
        float* gmw = g_M + (size_t)b * 16384;
#pragma unroll 4
        for (int e = 0; e < 32; e++) {
            int n = e * 8 + nb;
            float4 w = *(float4*)&sww[n * 4];
            float v = (n == lu0) ? 0.0f : sM[n * 65 + d];
            v += w.x * k0 + w.y * k1 + w.z * k2 + w.w * k3;
            sM[n * 65 + d] = v;
            gmw[n * 64 + d] = v;
        }
    }
    __syncthreads();

    // row norms + cosine sims: 2 threads per row
    {
        const int row = tid >> 1, hf = tid & 1;
        const float* mrow = sM + row * 65 + hf * 32;
        const float* kb = sk + hf * 32;
        float s = 0, d0 = 0, d1 = 0, d2 = 0, d3 = 0;
#pragma unroll
        for (int dd = 0; dd < 32; dd += 4) {
            float4 kk0 = *(const float4*)&kb[dd];
            float4 kk1 = *(const float4*)&kb[64 + dd];
            float4 kk2 = *(const float4*)&kb[128 + dd];
            float4 kk3 = *(const float4*)&kb[192 + dd];
            float m0 = mrow[dd], m1 = mrow[dd + 1], m2 = mrow[dd + 2], m3 = mrow[dd + 3];
            s  += m0 * m0 + m1 * m1 + m2 * m2 + m3 * m3;
            d0 += m0 * kk0.x + m1 * kk0.y + m2 * kk0.z + m3 * kk0.w;
            d1 += m0 * kk1.x + m1 * kk1.y + m2 * kk1.z + m3 * kk1.w;
            d2 += m0 * kk2.x + m1 * kk2.y + m2 * kk2.z + m3 * kk2.w;
            d3 += m0 * kk3.x + m1 * kk3.y + m2 * kk3.z + m3 * kk3.w;
        }
        s  += __shfl_xor_sync(0xffffffffu, s, 1);
        d0 += __shfl_xor_sync(0xffffffffu, d0, 1);
        d1 += __shfl_xor_sync(0xffffffffu, d1, 1);
        d2 += __shfl_xor_sync(0xffffffffu, d2, 1);
        d3 += __shfl_xor_sync(0xffffffffu, d3, 1);
        if (hf == 0) {
            float inv = 1.0f / (sqrtf(s) + EPSF);
            ssim[row]       = d0 * inv * sex[0];
            ssim[256 + row] = d1 * inv * sex[1];
            ssim[512 + row] = d2 * inv * sex[2];
            ssim[768 + row] = d3 * inv * sex[3];
        }
    }
    __syncthreads();

    // softmax per head (warp-shuffle)
    float e0, e1, e2, e3;
    float* srow = 0;
    int gH = 0;
    if (tid < 256) {
        gH = tid >> 6;
        const int j = tid & 63;
        srow = ssim + gH * 256 + j;
        float v0 = srow[0], v1 = srow[64], v2 = srow[128], v3 = srow[192];
        float mx = fmaxf(fmaxf(v0, v1), fmaxf(v2, v3));
#pragma unroll
        for (int o = 16; o > 0; o >>= 1) mx = fmaxf(mx, __shfl_xor_sync(0xffffffffu, mx, o));
        if (lane == 0) ssoft[gH * 2 + ((tid >> 5) & 1)] = mx;
        e0 = v0; e1 = v1; e2 = v2; e3 = v3;
    }
    __syncthreads();
    if (tid < 256) {
        float mx = fmaxf(ssoft[gH * 2], ssoft[gH * 2 + 1]);
        e0 = expf(e0 - mx); e1 = expf(e1 - mx); e2 = expf(e2 - mx); e3 = expf(e3 - mx);
        float sum = e0 + e1 + e2 + e3;
#pragma unroll
        for (int o = 16; o > 0; o >>= 1) sum += __shfl_xor_sync(0xffffffffu, sum, o);
        if (lane == 0) ssoft[8 + gH * 2 + ((tid >> 5) & 1)] = sum;
    }
    __syncthreads();
    if (tid < 256) {
        float inv = 1.0f / (ssoft[8 + gH * 2] + ssoft[8 + gH * 2 + 1]);
        srow[0] = e0 * inv; srow[64] = e1 * inv; srow[128] = e2 * inv; srow[192] = e3 * inv;
        float wrs = (e0 + e1 + e2 + e3) * inv;
        float4 w = *(float4*)&sww[tid * 4];
        g_wu[b * 256 + tid] = GAMMA * swu[tid] + wrs + (w.x + w.y + w.z + w.w);
    }
    __syncthreads();
    if (tid < 256) {
        float* gwr = g_wr + (size_t)b * 1024;
        gwr[tid] = ssim[tid]; gwr[256 + tid] = ssim[256 + tid];
        gwr[512 + tid] = ssim[512 + tid]; gwr[768 + tid] = ssim[768 + tid];
    }

    // reads[r][d]
    {
        const int half = tid >> 8;
        const int r = (tid >> 6) & 3, dd = tid & 63;
        const float* wr2 = ssim + r * 256 + half * 128;
        const float* mbase = sM + half * 128 * 65;
        float acc = 0.0f;
#pragma unroll 4
        for (int n = 0; n < 128; n += 4) {
            float4 w = *(const float4*)&wr2[n];
            acc += w.x * mbase[n * 65 + dd] + w.y * mbase[(n + 1) * 65 + dd]
                 + w.z * mbase[(n + 2) * 65 + dd] + w.w * mbase[(n + 3) * 65 + dd];
        }
        spR[tid] = acc;
    }
    __syncthreads();
    if (tid < 256) {
        float v = spR[tid] + spR[tid + 256];
        sreads[tid] = v;
        g_r[b * 256 + tid] = v;
    }
    __syncthreads();

    // output head
    if (tid < 256) {
        const float* w1 = Wout + (size_t)tid * 5;
        const float* w2 = Wout + (size_t)(256 + tid) * 5;
        float hv = sh[tid], rv = sreads[tid];
        float p0 = hv * w1[0] + rv * w2[0];
        float p1 = hv * w1[1] + rv * w2[1];
        float p2 = hv * w1[2] + rv * w2[2];
        float p3 = hv * w1[3] + rv * w2[3];
        float p4 = hv * w1[4] + rv * w2[4];
#pragma unroll
        for (int o = 16; o > 0; o >>= 1) {
            p0 += __shfl_xor_sync(0xffffffffu, p0, o);
            p1 += __shfl_xor_sync(0xffffffffu, p1, o);
            p2 += __shfl_xor_sync(0xffffffffu, p2, o);
            p3 += __shfl_xor_sync(0xffffffffu, p3, o);
            p4 += __shfl_xor_sync(0xffffffffu, p4, o);
        }
        if (lane == 0) {
            swp[wid * 5 + 0] = p0; swp[wid * 5 + 1] = p1; swp[wid * 5 + 2] = p2;
            swp[wid * 5 + 3] = p3; swp[wid * 5 + 4] = p4;
        }
    }
    __syncthreads();
    if (tid == 0) {
        float l[5];
#pragma unroll
        for (int c = 0; c < 5; c++) {
            float s = bout[c];
#pragma unroll
            for (int w = 0; w < 8; w++) s += swp[w * 5 + c];
            l[c] = s;
        }
        float mx = l[0];
#pragma unroll
        for (int c = 1; c < 5; c++) mx = fmaxf(mx, l[c]);
        float e[5], s = 0.0f;
#pragma unroll
        for (int c = 0; c < 5; c++) { e[c] = expf(l[c] - mx); s += e[c]; }
        float inv = 1.0f / s;
        float* o = out + ((size_t)b * TSTEPS + t) * 5;
#pragma unroll
        for (int c = 0; c < 5; c++) o[c] = e[c] * inv;
    }
}

// ---------- launch ----------
extern "C" void kernel_launch(void* const* d_in, const int* in_sizes, int n_in,
                              void* d_out, int out_size) {
    const float* X    = (const float*)d_in[0];
    const int*   tgt  = (const int*)d_in[1];
    const float* Wih  = (const float*)d_in[2];
    const float* Whh  = (const float*)d_in[3];
    const float* bl   = (const float*)d_in[4];
    const float* Wkp  = (const float*)d_in[5];
    const float* bkp  = (const float*)d_in[6];
    const float* Wout = (const float*)d_in[7];
    const float* bout = (const float*)d_in[8];
    float* out = (float*)d_out;

    cudaFuncSetAttribute(k4_mem, cudaFuncAttributeMaxDynamicSharedMemorySize, K4_BYTES);

    k_init<<<16384, 256>>>();
    k1_xw<<<dim3(16, 200), 256>>>(X, tgt, Wih, bl);
    for (int t = 0; t < TSTEPS; t++) {
        k2_step<<<dim3(8, 16), 256>>>(Wih, Whh, t);
        k4_mem<<<256, 512, K4_BYTES>>>(Wkp, bkp, Wout, bout, out, t);
    }
}

// round 11
// speedup vs baseline: 1.0160x; 1.0160x over previous
#include <cuda_runtime.h>
#include <math.h>

#define BATCH 256
#define TSTEPS 50
#define INSZ 400
#define G4 1024
#define GAMMA 0.95f
#define EPSF 1e-8f

// ---------- device scratch ----------
__device__ float g_xw[TSTEPS * BATCH * G4];
__device__ float g_h[BATCH * 256];
__device__ float g_c[BATCH * 256];
__device__ float g_r[BATCH * 256];
__device__ float g_M[BATCH * 256 * 64];
__device__ float g_wr[BATCH * 4 * 256];
__device__ float g_wu[BATCH * 256];
__device__ float g_pp[16 * 256 * 260];   // kp partials: [unit_tile][batch][col]

__device__ __forceinline__ float sigf(float x) { return 1.0f / (1.0f + expf(-x)); }

// ---------- init ----------
__global__ void k_init() {
    int i = blockIdx.x * blockDim.x + threadIdx.x;
    if (i < BATCH * 256 * 64) g_M[i] = 1e-6f;
    if (i < BATCH * 1024) g_wr[i] = 1.0f / 256.0f;
    if (i < BATCH * 256) {
        g_h[i] = 0.0f; g_c[i] = 0.0f; g_r[i] = 0.0f;
        g_wu[i] = 1.0f / 256.0f;
    }
}

// ---------- K1: time-parallel input GEMM (R8 scalar version) ----------
__global__ __launch_bounds__(256) void k1_xw(
    const float* __restrict__ X, const int* __restrict__ tgt,
    const float* __restrict__ Wih, const float* __restrict__ bl)
{
    __shared__ float As[16][68];
    __shared__ float Bs[16][64];
    const int tid = threadIdx.x;
    const int tx = tid & 15, ty = tid >> 4;
    const int m0 = blockIdx.y * 64, n0 = blockIdx.x * 64;
    const int arow = tid >> 2, akq = tid & 3;
    const int bk = tid >> 4, bc = tid & 15;
    float acc[4][4] = {};
    for (int kt = 0; kt < 25; kt++) {
        float4 av = *(const float4*)(X + (size_t)(m0 + arow) * INSZ + kt * 16 + akq * 4);
        As[akq * 4 + 0][arow] = av.x; As[akq * 4 + 1][arow] = av.y;
        As[akq * 4 + 2][arow] = av.z; As[akq * 4 + 3][arow] = av.w;
        *(float4*)&Bs[bk][bc * 4] =
            *(const float4*)(Wih + (size_t)(kt * 16 + bk) * G4 + n0 + bc * 4);
        __syncthreads();
#pragma unroll
        for (int k = 0; k < 16; k++) {
            float4 a = *(float4*)&As[k][ty * 4];
            float4 b = *(float4*)&Bs[k][tx * 4];
            acc[0][0] += a.x * b.x; acc[0][1] += a.x * b.y; acc[0][2] += a.x * b.z; acc[0][3] += a.x * b.w;
            acc[1][0] += a.y * b.x; acc[1][1] += a.y * b.y; acc[1][2] += a.y * b.z; acc[1][3] += a.y * b.w;
            acc[2][0] += a.z * b.x; acc[2][1] += a.z * b.y; acc[2][2] += a.z * b.z; acc[2][3] += a.z * b.w;
            acc[3][0] += a.w * b.x; acc[3][1] += a.w * b.y; acc[3][2] += a.w * b.z; acc[3][3] += a.w * b.w;
        }
        __syncthreads();
    }
#pragma unroll
    for (int i = 0; i < 4; i++) {
        int m = m0 + ty * 4 + i;
        int bb = m / TSTEPS, t = m % TSTEPS;
        const float* offrow = (t > 0) ? (Wih + (size_t)(400 + tgt[m - 1]) * G4) : (const float*)0;
        float* dst = g_xw + ((size_t)t * BATCH + bb) * G4 + n0 + tx * 4;
#pragma unroll
        for (int j = 0; j < 4; j++) {
            int c = n0 + tx * 4 + j;
            float v = acc[i][j] + bl[c];
            if (offrow) v += offrow[c];
            dst[j] = v;
        }
    }
}

// ---------- K2: recurrent GEMM + LSTM (R8 core) + kp-partial epilogue ----------
// dynamic smem layout (floats):
//   GEMM phase:   As = dyn[0 .. 1056)   [2][16][33]
//                 Bs = dyn[1056 .. 3232) [2][16][68]
//   epilogue:     sh2 = dyn[0 .. 544)    [32][17]
//                 wk  = dyn[544 .. 4736) [16][262]
//                 spp = dyn[4736 .. 13056) [32][260]
#define K2_FLOATS 13056
#define K2_BYTES (K2_FLOATS * 4)

__global__ __launch_bounds__(256) void k2_step(
    const float* __restrict__ Wih, const float* __restrict__ Whh,
    const float* __restrict__ Wkp, int t)
{
    extern __shared__ float dyn2[];
    float* As = dyn2;            // [2][16][33]
    float* Bs = dyn2 + 1056;     // [2][16][68]
    const int tid = threadIdx.x;
    const int tx = tid & 15, ty = tid >> 4;
    const int b0 = blockIdx.x * 32, u0 = blockIdx.y * 16;
    const int arow = tid >> 3, akq = tid & 7;
    const int bk = tid >> 4, bu = tid & 15;
    const float* WihR = Wih + (size_t)405 * G4;

    // prefetch epilogue operands
    const int uP = u0 + tx;
    const int bP0 = b0 + ty * 2, bP1 = bP0 + 1;
    const float* xwA = g_xw + ((size_t)t * BATCH + bP0) * G4;
    const float* xwB = g_xw + ((size_t)t * BATCH + bP1) * G4;
    float xA0 = xwA[uP], xA1 = xwA[256 + uP], xA2 = xwA[512 + uP], xA3 = xwA[768 + uP];
    float xB0 = xwB[uP], xB1 = xwB[256 + uP], xB2 = xwB[512 + uP], xB3 = xwB[768 + uP];
    float cA = g_c[bP0 * 256 + uP], cB = g_c[bP1 * 256 + uP];

    // tile 0 -> buffer 0
    {
        float2 av = *(const float2*)(g_r + (size_t)(b0 + arow) * 256 + akq * 2);
        As[0 * 528 + (akq * 2) * 33 + arow] = av.x;
        As[0 * 528 + (akq * 2 + 1) * 33 + arow] = av.y;
        const float* wrow = WihR + (size_t)bk * G4 + u0 + bu;
        Bs[0 * 1088 + bk * 68 + bu * 4 + 0] = wrow[0];
        Bs[0 * 1088 + bk * 68 + bu * 4 + 1] = wrow[256];
        Bs[0 * 1088 + bk * 68 + bu * 4 + 2] = wrow[512];
        Bs[0 * 1088 + bk * 68 + bu * 4 + 3] = wrow[768];
    }
    __syncthreads();

    float acc[2][4] = {};
    for (int kt = 0; kt < 32; kt++) {
        const int cur = kt & 1;
        float2 avn = make_float2(0.f, 0.f);
        float bgn0 = 0.f, bgn1 = 0.f, bgn2 = 0.f, bgn3 = 0.f;
        if (kt < 31) {
            const int kn = kt + 1;
            const float* src = (kn < 16) ? g_r : g_h;
            avn = *(const float2*)(src + (size_t)(b0 + arow) * 256 + (kn & 15) * 16 + akq * 2);
            const float* W = (kn < 16) ? WihR : Whh;
            const float* wrow = W + (size_t)((kn & 15) * 16 + bk) * G4 + u0 + bu;
            bgn0 = wrow[0]; bgn1 = wrow[256]; bgn2 = wrow[512]; bgn3 = wrow[768];
        }
#pragma unroll
        for (int k = 0; k < 16; k++) {
            float a0 = As[cur * 528 + k * 33 + ty * 2];
            float a1 = As[cur * 528 + k * 33 + ty * 2 + 1];
            float bx = Bs[cur * 1088 + k * 68 + tx * 4 + 0];
            float by = Bs[cur * 1088 + k * 68 + tx * 4 + 1];
            float bz = Bs[cur * 1088 + k * 68 + tx * 4 + 2];
            float bw = Bs[cur * 1088 + k * 68 + tx * 4 + 3];
            acc[0][0] += a0 * bx; acc[0][1] += a0 * by; acc[0][2] += a0 * bz; acc[0][3] += a0 * bw;
            acc[1][0] += a1 * bx; acc[1][1] += a1 * by; acc[1][2] += a1 * bz; acc[1][3] += a1 * bw;
        }
        if (kt < 31) {
            const int nxt = 1 - cur;
            As[nxt * 528 + (akq * 2) * 33 + arow] = avn.x;
            As[nxt * 528 + (akq * 2 + 1) * 33 + arow] = avn.y;
            Bs[nxt * 1088 + bk * 68 + bu * 4 + 0] = bgn0;
            Bs[nxt * 1088 + bk * 68 + bu * 4 + 1] = bgn1;
            Bs[nxt * 1088 + bk * 68 + bu * 4 + 2] = bgn2;
            Bs[nxt * 1088 + bk * 68 + bu * 4 + 3] = bgn3;
            __syncthreads();
        }
    }
    float hhA, hhB;
    {
        float gi = acc[0][0] + xA0, gf = acc[0][1] + xA1, gg = acc[0][2] + xA2, go = acc[0][3] + xA3;
        float cc = sigf(gf) * cA + sigf(gi) * tanhf(gg);
        g_c[bP0 * 256 + uP] = cc;
        hhA = sigf(go) * tanhf(cc);
        g_h[bP0 * 256 + uP] = hhA;
    }
    {
        float gi = acc[1][0] + xB0, gf = acc[1][1] + xB1, gg = acc[1][2] + xB2, go = acc[1][3] + xB3;
        float cc = sigf(gf) * cB + sigf(gi) * tanhf(gg);
        g_c[bP1 * 256 + uP] = cc;
        hhB = sigf(go) * tanhf(cc);
        g_h[bP1 * 256 + uP] = hhB;
    }

    // ---- epilogue: partial kp GEMM for this unit tile ----
    // p_part[b][c] = sum_{u in [u0,u0+16)} h[b][u] * Wkp[u][c]
    float* sh2 = dyn2;           // [32][17]
    float* wk  = dyn2 + 544;     // [16][262]
    float* spp = dyn2 + 4736;    // [32][260]
    __syncthreads();             // protect As/Bs readers before overlay
    sh2[(ty * 2) * 17 + tx]     = hhA;
    sh2[(ty * 2 + 1) * 17 + tx] = hhB;
    for (int e = tid; e < 16 * 260; e += 256) {
        int r = e / 260, c = e - r * 260;
        wk[r * 262 + c] = Wkp[(size_t)(u0 + r) * 260 + c];
    }
    __syncthreads();
    {
        const int bi = tid >> 3, c0 = tid & 7;
        float hreg[16];
#pragma unroll
        for (int u = 0; u < 16; u++) hreg[u] = sh2[bi * 17 + u];
        for (int c = c0; c < 260; c += 8) {
            float a = 0.0f;
#pragma unroll
            for (int u = 0; u < 16; u++) a += hreg[u] * wk[u * 262 + c];
            spp[bi * 260 + c] = a;
        }
    }
    __syncthreads();
    {
        float* dst = g_pp + ((size_t)blockIdx.y * 256 + b0) * 260;
        for (int e = tid; e < 32 * 260; e += 256)
            dst[e] = spp[e];
    }
}

// ---------- K4: 512-thread memory module (kp partial-sum instead of GEMV) ----------
#define O_M     0        // 256*65
#define O_K     16640    // 256
#define O_SIM   16896    // 1024
#define O_WW    17920    // 1024
#define O_WU    18944    // 256
#define O_H     19200    // 256
#define O_RD    19456    // 256
#define O_PR    19712    // 512
#define O_WP    20224    // 40
#define O_EX    20264    // 16
#define O_SOFT  20280    // 16
#define O_LU    20296    // 4 (int)
#define K4_FLOATS 20304
#define K4_BYTES (K4_FLOATS * 4)

__global__ __launch_bounds__(512) void k4_mem(
    const float* __restrict__ bkp,
    const float* __restrict__ Wout, const float* __restrict__ bout,
    float* __restrict__ out, int t)
{
    extern __shared__ float sm[];
    float* sM     = sm + O_M;
    float* sk     = sm + O_K;
    float* ssim   = sm + O_SIM;
    float* sww    = sm + O_WW;
    float* swu    = sm + O_WU;
    float* sh     = sm + O_H;
    float* sreads = sm + O_RD;
    float* spR    = sm + O_PR;
    float* swp    = sm + O_WP;
    float* sex    = sm + O_EX;
    float* ssoft  = sm + O_SOFT;
    int*   slu    = (int*)(sm + O_LU);

    const int b = blockIdx.x;
    const int tid = threadIdx.x;
    const int lane = tid & 31, wid = tid >> 5;

    // ---- phase 0: loads + kp partial-sum (all independent) ----
    if (tid < 256) {
        swu[tid] = g_wu[b * 256 + tid];
        sh[tid]  = g_h[b * 256 + tid];
    }
    if (tid < 260) {
        float s = bkp[tid];
#pragma unroll
        for (int q = 0; q < 16; q++)
            s += g_pp[((size_t)q * 256 + b) * 260 + tid];
        if (tid < 256) sk[tid] = tanhf(s);
        else sex[4 + (tid - 256)] = sigf(s);
    }
    {
        const float4* gm4 = (const float4*)(g_M + (size_t)b * 16384);
#pragma unroll
        for (int e = 0; e < 8; e++) {
            float4 v = gm4[e * 512 + tid];
            int gidx = (e * 512 + tid) * 4;
            int n = gidx >> 6, d = gidx & 63;
            float* dst = sM + n * 65 + d;
            dst[0] = v.x; dst[1] = v.y; dst[2] = v.z; dst[3] = v.w;
        }
    }
    __syncthreads();

    // key norms (warps 0-3) || top-4 least-used (warp 4)
    if (wid < 4) {
        float v0 = sk[wid * 64 + lane], v1 = sk[wid * 64 + lane + 32];
        float s = v0 * v0 + v1 * v1;
#pragma unroll
        for (int o = 16; o > 0; o >>= 1) s += __shfl_xor_sync(0xffffffffu, s, o);
        if (lane == 0) sex[wid] = 1.0f / (sqrtf(s) + EPSF);
    } else if (wid == 4) {
        float v[8];
#pragma unroll
        for (int j = 0; j < 8; j++) v[j] = swu[j * 32 + lane];
#pragma unroll
        for (int r = 0; r < 4; r++) {
            float bv = v[0]; int bi = lane;
#pragma unroll
            for (int j = 1; j < 8; j++) {
                int idx = j * 32 + lane;
                if (v[j] < bv) { bv = v[j]; bi = idx; }
            }
#pragma unroll
            for (int o = 16; o > 0; o >>= 1) {
                float ov = __shfl_xor_sync(0xffffffffu, bv, o);
                int   oi = __shfl_xor_sync(0xffffffffu, bi, o);
                if (ov < bv || (ov == bv && oi < bi)) { bv = ov; bi = oi; }
            }
            if (lane == 0) slu[r] = bi;
#pragma unroll
            for (int j = 0; j < 8; j++)
                if (bi == j * 32 + lane) v[j] = 3.0e38f;
        }
    }
    __syncthreads();

    if (tid < 256) {
        float a0 = sex[4], a1 = sex[5], a2 = sex[6], a3 = sex[7];
        const float* wr = g_wr + (size_t)b * 1024;
        float4 w;
        w.x = a0 * wr[tid]       + (1.0f - a0) * ((tid == slu[0]) ? 1.0f : 0.0f);
        w.y = a1 * wr[256 + tid] + (1.0f - a1) * ((tid == slu[1]) ? 1.0f : 0.0f);
        w.z = a2 * wr[512 + tid] + (1.0f - a2) * ((tid == slu[2]) ? 1.0f : 0.0f);
        w.w = a3 * wr[768 + tid] + (1.0f - a3) * ((tid == slu[3]) ? 1.0f : 0.0f);
        *(float4*)&sww[tid * 4] = w;
    }
    __syncthreads();

    // erase + additive write; persist M
    {
        const int d = tid & 63, nb = tid >> 6;
        const int lu0 = slu[0];
        const float k0 = sk[d], k1 = sk[64 + d], k2 = sk[128 + d], k3 = sk[192 + d];
        float* gmw = g_M + (size_t)b * 16384;
#pragma unroll 4
        for (int e = 0; e < 32; e++) {
            int n = e * 8 + nb;
            float4 w = *(float4*)&sww[n * 4];
            float v = (n == lu0) ? 0.0f : sM[n * 65 + d];
            v += w.x * k0 + w.y * k1 + w.z * k2 + w.w * k3;
            sM[n * 65 + d] = v;
            gmw[n * 64 + d] = v;
        }
    }
    __syncthreads();

    // row norms + cosine sims: 2 threads per row
    {
        const int row = tid >> 1, hf = tid & 1;
        const float* mrow = sM + row * 65 + hf * 32;
        const float* kb = sk + hf * 32;
        float s = 0, d0 = 0, d1 = 0, d2 = 0, d3 = 0;
#pragma unroll
        for (int dd = 0; dd < 32; dd += 4) {
            float4 kk0 = *(const float4*)&kb[dd];
            float4 kk1 = *(const float4*)&kb[64 + dd];
            float4 kk2 = *(const float4*)&kb[128 + dd];
            float4 kk3 = *(const float4*)&kb[192 + dd];
            float m0 = mrow[dd], m1 = mrow[dd + 1], m2 = mrow[dd + 2], m3 = mrow[dd + 3];
            s  += m0 * m0 + m1 * m1 + m2 * m2 + m3 * m3;
            d0 += m0 * kk0.x + m1 * kk0.y + m2 * kk0.z + m3 * kk0.w;
            d1 += m0 * kk1.x + m1 * kk1.y + m2 * kk1.z + m3 * kk1.w;
            d2 += m0 * kk2.x + m1 * kk2.y + m2 * kk2.z + m3 * kk2.w;
            d3 += m0 * kk3.x + m1 * kk3.y + m2 * kk3.z + m3 * kk3.w;
        }
        s  += __shfl_xor_sync(0xffffffffu, s, 1);
        d0 += __shfl_xor_sync(0xffffffffu, d0, 1);
        d1 += __shfl_xor_sync(0xffffffffu, d1, 1);
        d2 += __shfl_xor_sync(0xffffffffu, d2, 1);
        d3 += __shfl_xor_sync(0xffffffffu, d3, 1);
        if (hf == 0) {
            float inv = 1.0f / (sqrtf(s) + EPSF);
            ssim[row]       = d0 * inv * sex[0];
            ssim[256 + row] = d1 * inv * sex[1];
            ssim[512 + row] = d2 * inv * sex[2];
            ssim[768 + row] = d3 * inv * sex[3];
        }
    }
    __syncthreads();

    // softmax per head (warp-shuffle)
    float e0, e1, e2, e3;
    float* srow = 0;
    int gH = 0;
    if (tid < 256) {
        gH = tid >> 6;
        const int j = tid & 63;
        srow = ssim + gH * 256 + j;
        float v0 = srow[0], v1 = srow[64], v2 = srow[128], v3 = srow[192];
        float mx = fmaxf(fmaxf(v0, v1), fmaxf(v2, v3));
#pragma unroll
        for (int o = 16; o > 0; o >>= 1) mx = fmaxf(mx, __shfl_xor_sync(0xffffffffu, mx, o));
        if (lane == 0) ssoft[gH * 2 + ((tid >> 5) & 1)] = mx;
        e0 = v0; e1 = v1; e2 = v2; e3 = v3;
    }
    __syncthreads();
    if (tid < 256) {
        float mx = fmaxf(ssoft[gH * 2], ssoft[gH * 2 + 1]);
        e0 = expf(e0 - mx); e1 = expf(e1 - mx); e2 = expf(e2 - mx); e3 = expf(e3 - mx);
        float sum = e0 + e1 + e2 + e3;
#pragma unroll
        for (int o = 16; o > 0; o >>= 1) sum += __shfl_xor_sync(0xffffffffu, sum, o);
        if (lane == 0) ssoft[8 + gH * 2 + ((tid >> 5) & 1)] = sum;
    }
    __syncthreads();
    if (tid < 256) {
        float inv = 1.0f / (ssoft[8 + gH * 2] + ssoft[8 + gH * 2 + 1]);
        srow[0] = e0 * inv; srow[64] = e1 * inv; srow[128] = e2 * inv; srow[192] = e3 * inv;
        float wrs = (e0 + e1 + e2 + e3) * inv;
        float4 w = *(float4*)&sww[tid * 4];
        g_wu[b * 256 + tid] = GAMMA * swu[tid] + wrs + (w.x + w.y + w.z + w.w);
    }
    __syncthreads();
    if (tid < 256) {
        float* gwr = g_wr + (size_t)b * 1024;
        gwr[tid] = ssim[tid]; gwr[256 + tid] = ssim[256 + tid];
        gwr[512 + tid] = ssim[512 + tid]; gwr[768 + tid] = ssim[768 + tid];
    }

    // reads[r][d]
    {
        const int half = tid >> 8;
        const int r = (tid >> 6) & 3, dd = tid & 63;
        const float* wr2 = ssim + r * 256 + half * 128;
        const float* mbase = sM + half * 128 * 65;
        float acc = 0.0f;
#pragma unroll 4
        for (int n = 0; n < 128; n += 4) {
            float4 w = *(const float4*)&wr2[n];
            acc += w.x * mbase[n * 65 + dd] + w.y * mbase[(n + 1) * 65 + dd]
                 + w.z * mbase[(n + 2) * 65 + dd] + w.w * mbase[(n + 3) * 65 + dd];
        }
        spR[tid] = acc;
    }
    __syncthreads();
    if (tid < 256) {
        float v = spR[tid] + spR[tid + 256];
        sreads[tid] = v;
        g_r[b * 256 + tid] = v;
    }
    __syncthreads();

    // output head
    if (tid < 256) {
        const float* w1 = Wout + (size_t)tid * 5;
        const float* w2 = Wout + (size_t)(256 + tid) * 5;
        float hv = sh[tid], rv = sreads[tid];
        float p0 = hv * w1[0] + rv * w2[0];
        float p1 = hv * w1[1] + rv * w2[1];
        float p2 = hv * w1[2] + rv * w2[2];
        float p3 = hv * w1[3] + rv * w2[3];
        float p4 = hv * w1[4] + rv * w2[4];
#pragma unroll
        for (int o = 16; o > 0; o >>= 1) {
            p0 += __shfl_xor_sync(0xffffffffu, p0, o);
            p1 += __shfl_xor_sync(0xffffffffu, p1, o);
            p2 += __shfl_xor_sync(0xffffffffu, p2, o);
            p3 += __shfl_xor_sync(0xffffffffu, p3, o);
            p4 += __shfl_xor_sync(0xffffffffu, p4, o);
        }
        if (lane == 0) {
            swp[wid * 5 + 0] = p0; swp[wid * 5 + 1] = p1; swp[wid * 5 + 2] = p2;
            swp[wid * 5 + 3] = p3; swp[wid * 5 + 4] = p4;
        }
    }
    __syncthreads();
    if (tid == 0) {
        float l[5];
#pragma unroll
        for (int c = 0; c < 5; c++) {
            float s = bout[c];
#pragma unroll
            for (int w = 0; w < 8; w++) s += swp[w * 5 + c];
            l[c] = s;
        }
        float mx = l[0];
#pragma unroll
        for (int c = 1; c < 5; c++) mx = fmaxf(mx, l[c]);
        float e[5], s = 0.0f;
#pragma unroll
        for (int c = 0; c < 5; c++) { e[c] = expf(l[c] - mx); s += e[c]; }
        float inv = 1.0f / s;
        float* o = out + ((size_t)b * TSTEPS + t) * 5;
#pragma unroll
        for (int c = 0; c < 5; c++) o[c] = e[c] * inv;
    }
}

// ---------- launch ----------
extern "C" void kernel_launch(void* const* d_in, const int* in_sizes, int n_in,
                              void* d_out, int out_size) {
    const float* X    = (const float*)d_in[0];
    const int*   tgt  = (const int*)d_in[1];
    const float* Wih  = (const float*)d_in[2];
    const float* Whh  = (const float*)d_in[3];
    const float* bl   = (const float*)d_in[4];
    const float* Wkp  = (const float*)d_in[5];
    const float* bkp  = (const float*)d_in[6];
    const float* Wout = (const float*)d_in[7];
    const float* bout = (const float*)d_in[8];
    float* out = (float*)d_out;

    cudaFuncSetAttribute(k2_step, cudaFuncAttributeMaxDynamicSharedMemorySize, K2_BYTES);
    cudaFuncSetAttribute(k4_mem,  cudaFuncAttributeMaxDynamicSharedMemorySize, K4_BYTES);

    k_init<<<16384, 256>>>();
    k1_xw<<<dim3(16, 200), 256>>>(X, tgt, Wih, bl);
    for (int t = 0; t < TSTEPS; t++) {
        k2_step<<<dim3(8, 16), 256, K2_BYTES>>>(Wih, Whh, Wkp, t);
        k4_mem<<<256, 512, K4_BYTES>>>(bkp, Wout, bout, out, t);
    }
}